// round 9
// baseline (speedup 1.0000x reference)
#include <cuda_runtime.h>

// FFM forward: B=16384, F=6 fields, LATENT=16.
// Flat-work-list gather: 370 embedding rows/sample, 4 lanes per row (float4),
// striped over 64 row-units of a 256-thread block. Register-staged loads for
// MLP=6, shared-memory atomic accumulation, single-warp finalize.

#define NF      6
#define LATENT  16
#define TOTIDX  74    // sum of SEQ
#define NROWS   370   // 5 slots * 74 rows
#define NTHREADS 256
#define NUNITS  64    // NTHREADS / 4
#define MAXK    6     // ceil(370/64)

struct FfmParams {
    const int*   x[NF];
    const float* E[NF];   // (F-1, DIMS[i], LATENT) row-major
    const float* L[NF];   // (DIMS[i], 1)
    const float* Wd;      // (F, 1)
    const float* bd;      // (1,)
    float*       out;     // (B, 1)
};

// Map flat row r in [0,370) -> embedding base, dim, index-offset, vacc slot, seqpos.
// Row layout: field-major, slot-major within field, seq innermost.
// bases: f0:[0,5) f1:[5,10) f2:[10,260) f3:[260,360) f4:[360,365) f5:[365,370)
__device__ __forceinline__ void row_decode(const FfmParams& p, int r,
                                           const float*& Eb, long long& dim,
                                           int& off, int& vslot, int& slot, int& q) {
    if (r < 5)        { Eb = p.E[0]; dim = 1000000; off = 0;  slot = r;       q = 0; vslot = 0*5 + slot; }
    else if (r < 10)  { Eb = p.E[1]; dim = 500000;  off = 1;  slot = r - 5;   q = 0; vslot = 1*5 + slot; }
    else if (r < 260) { Eb = p.E[2]; dim = 500000;  off = 2;  int m = r - 10;
                        slot = m / 50; q = m % 50; vslot = 2*5 + slot; }
    else if (r < 360) { Eb = p.E[3]; dim = 100000;  off = 52; int m = r - 260;
                        slot = m / 20; q = m % 20; vslot = 3*5 + slot; }
    else if (r < 365) { Eb = p.E[4]; dim = 10000;   off = 72; slot = r - 360; q = 0; vslot = 4*5 + slot; }
    else              { Eb = p.E[5]; dim = 1000;    off = 73; slot = r - 365; q = 0; vslot = 5*5 + slot; }
}

__global__ __launch_bounds__(NTHREADS) void ffm_kernel(FfmParams p) {
    const int b    = blockIdx.x;
    const int tid  = threadIdx.x;
    const int unit = tid >> 2;     // 0..63
    const int lane = tid & 3;      // float4 lane within a 16-float row

    __shared__ int   sidx[TOTIDX];
    __shared__ float vacc[NF * 5][LATENT];   // summed (not yet meaned) pair embeddings
    __shared__ float lsum[NF];               // summed linear terms

    // ---- zero accumulators + preload indices ----
    for (int k = tid; k < NF * 5 * LATENT; k += NTHREADS)
        (&vacc[0][0])[k] = 0.0f;
    if (tid < NF) lsum[tid] = 0.0f;

    if (tid == 0)       sidx[0]   = p.x[0][b];
    else if (tid == 1)  sidx[1]   = p.x[1][b];
    else if (tid < 52)  sidx[tid] = p.x[2][(long long)b * 50 + (tid - 2)];
    else if (tid < 72)  sidx[tid] = p.x[3][(long long)b * 20 + (tid - 52)];
    else if (tid == 72) sidx[72]  = p.x[4][b];
    else if (tid == 73) sidx[73]  = p.x[5][b];
    __syncthreads();

    // ---- phase 1: issue all embedding loads (register-staged, MLP=MAXK) ----
    float4 vals[MAXK];
    int    dsts[MAXK];      // vacc slot, or -1 if past end of work list
#pragma unroll
    for (int k = 0; k < MAXK; ++k) {
        const int r = unit + k * NUNITS;
        dsts[k] = -1;
        if (r < NROWS) {
            const float* Eb; long long dim; int off, vslot, slot, q;
            row_decode(p, r, Eb, dim, off, vslot, slot, q);
            const int idx = sidx[off + q];
            vals[k] = __ldg((const float4*)Eb + ((long long)slot * dim + idx) * 4 + lane);
            dsts[k] = vslot;
        }
    }

    // ---- phase 2: shared-memory accumulation ----
#pragma unroll
    for (int k = 0; k < MAXK; ++k) {
        if (dsts[k] >= 0) {
            float* d = &vacc[dsts[k]][lane * 4];
            atomicAdd(d + 0, vals[k].x);
            atomicAdd(d + 1, vals[k].y);
            atomicAdd(d + 2, vals[k].z);
            atomicAdd(d + 3, vals[k].w);
        }
    }

    // ---- linear-term gather (74 scalar loads) ----
    if (tid < TOTIDX) {
        const float* Lb; int fi;
        if (tid == 0)       { Lb = p.L[0]; fi = 0; }
        else if (tid == 1)  { Lb = p.L[1]; fi = 1; }
        else if (tid < 52)  { Lb = p.L[2]; fi = 2; }
        else if (tid < 72)  { Lb = p.L[3]; fi = 3; }
        else if (tid == 72) { Lb = p.L[4]; fi = 4; }
        else                { Lb = p.L[5]; fi = 5; }
        atomicAdd(&lsum[fi], __ldg(Lb + sidx[tid]));
    }
    __syncthreads();

    // ---- finalize: FM interaction + linear + sigmoid ----
    if (tid < 16) {
        constexpr float SC[NF] = {1.0f, 1.0f, 1.0f/50.0f, 1.0f/20.0f, 1.0f, 1.0f};
        float fmp = 0.0f;
#pragma unroll
        for (int i = 0; i < NF; ++i) {
#pragma unroll
            for (int j = i + 1; j < NF; ++j) {
                // pair_emb(i,j) slot = j-1 (j>i); pair_emb(j,i) slot = i (i<j)
                fmp += (vacc[i*5 + (j-1)][tid] * SC[i]) * (vacc[j*5 + i][tid] * SC[j]);
            }
        }
#pragma unroll
        for (int o = 8; o > 0; o >>= 1)
            fmp += __shfl_down_sync(0x0000FFFFu, fmp, o);

        if (tid == 0) {
            float lin = __ldg(p.bd);
#pragma unroll
            for (int i = 0; i < NF; ++i)
                lin += lsum[i] * SC[i] * __ldg(p.Wd + i);
            lin = fmaxf(lin, 0.0f);
            const float z = lin + fmp;
            p.out[b] = 1.0f / (1.0f + __expf(-z));
        }
    }
}

extern "C" void kernel_launch(void* const* d_in, const int* in_sizes, int n_in,
                              void* d_out, int out_size) {
    FfmParams p;
    for (int i = 0; i < NF; ++i) p.x[i] = (const int*)d_in[i];   // x0..x5

    // setup_inputs() interleaves E and L: E0,L0,E1,L1,...,E5,L5 (auto-detect).
    const bool interleaved = (in_sizes[7] < 2000000);
    for (int i = 0; i < NF; ++i) {
        if (interleaved) {
            p.E[i] = (const float*)d_in[6 + 2 * i];
            p.L[i] = (const float*)d_in[7 + 2 * i];
        } else {
            p.E[i] = (const float*)d_in[6 + i];
            p.L[i] = (const float*)d_in[12 + i];
        }
    }
    p.Wd  = (const float*)d_in[18];
    p.bd  = (const float*)d_in[19];
    p.out = (float*)d_out;

    const int B = in_sizes[0];
    ffm_kernel<<<B, NTHREADS>>>(p);
}

// round 13
// speedup vs baseline: 2.5398x; 2.5398x over previous
#include <cuda_runtime.h>

// FFM forward: B=16384, F=6 fields, LATENT=16.
// One block (256 thr) per sample. 64 "units" of 4 lanes; unit = one float4 lane
// group over a 64B embedding row. Long seq fields split across units (10 rows
// each) -> MLP=10 per thread, fully unrolled LDG.128 batches, NO atomics:
// per-thread smem partials + deterministic reduction.

#define NF       6
#define TOTIDX   74
#define NTHREADS 256

struct FfmParams {
    const int*   x[NF];
    const float* E[NF];   // (F-1, DIMS[i], LATENT) row-major
    const float* L[NF];   // (DIMS[i], 1)
    const float* Wd;      // (F, 1)
    const float* bd;      // (1,)
    float*       out;     // (B, 1)
};

__global__ __launch_bounds__(NTHREADS) void ffm_kernel(FfmParams p) {
    constexpr int       SEQ[NF]  = {1, 1, 50, 20, 1, 1};
    constexpr int       OFF[NF]  = {0, 1, 2, 52, 72, 73};
    constexpr long long DIMS[NF] = {1000000, 500000, 500000, 100000, 10000, 1000};

    const int b    = blockIdx.x;
    const int tid  = threadIdx.x;
    const int unit = tid >> 2;     // 0..63
    const int lane = tid & 3;      // float4 lane within a 16-float row

    __shared__ int    sidx[TOTIDX];
    __shared__ float4 psum[NTHREADS];     // per-thread partial (unit, lane)
    __shared__ float  vsh[NF * 5][16];    // final mean-pooled pair embeddings
    __shared__ float  larr[TOTIDX];       // gathered linear-term elements
    __shared__ float  lsum[NF];           // per-field scaled linear sums

    // ---- preload indices (threads 0..73) ----
    if (tid == 0)       sidx[0]   = p.x[0][b];
    else if (tid == 1)  sidx[1]   = p.x[1][b];
    else if (tid < 52)  sidx[tid] = p.x[2][(long long)b * 50 + (tid - 2)];
    else if (tid < 72)  sidx[tid] = p.x[3][(long long)b * 20 + (tid - 52)];
    else if (tid == 72) sidx[72]  = p.x[4][b];
    else if (tid == 73) sidx[73]  = p.x[5][b];
    __syncthreads();

    // ---- phase 1: gather ----
    // unit map:  0..24  field2, slot=u/5,      seq [(u%5)*10, +10)
    //           25..34  field3, slot=(u-25)/2, seq [((u-25)%2)*10, +10)
    //           35..54  single-row fields: f0@35, f1@40, f4@45, f5@50 (+slot)
    //           55..63  (threads 220..255) linear-term gather
    if (unit < 25) {
        const int slot = unit / 5;
        const int s0   = (unit % 5) * 10;
        const float4* base = (const float4*)p.E[2] + (long long)slot * DIMS[2] * 4 + lane;
        float4 a = make_float4(0.f, 0.f, 0.f, 0.f);
#pragma unroll
        for (int t = 0; t < 10; ++t) {
            float4 e = __ldg(base + (long long)sidx[OFF[2] + s0 + t] * 4);
            a.x += e.x; a.y += e.y; a.z += e.z; a.w += e.w;
        }
        psum[tid] = a;
    } else if (unit < 35) {
        const int m    = unit - 25;
        const int slot = m >> 1;
        const int s0   = (m & 1) * 10;
        const float4* base = (const float4*)p.E[3] + (long long)slot * DIMS[3] * 4 + lane;
        float4 a = make_float4(0.f, 0.f, 0.f, 0.f);
#pragma unroll
        for (int t = 0; t < 10; ++t) {
            float4 e = __ldg(base + (long long)sidx[OFF[3] + s0 + t] * 4);
            a.x += e.x; a.y += e.y; a.z += e.z; a.w += e.w;
        }
        psum[tid] = a;
    } else if (unit < 55) {
        const int m = unit - 35;                  // 0..19
        const int f = (m < 5) ? 0 : (m < 10) ? 1 : (m < 15) ? 4 : 5;
        const int slot = m % 5;
        const float4* base = (const float4*)p.E[f] + (long long)slot * DIMS[f] * 4 + lane;
        psum[tid] = __ldg(base + (long long)sidx[OFF[f]] * 4);
    } else {
        // linear-term gather: 36 threads cover 74 indices
        const int k = tid - 220;                  // 0..35
        for (int l = k; l < TOTIDX; l += 36) {
            const float* Lb =
                (l == 0)  ? p.L[0] :
                (l == 1)  ? p.L[1] :
                (l < 52)  ? p.L[2] :
                (l < 72)  ? p.L[3] :
                (l == 72) ? p.L[4] : p.L[5];
            larr[l] = __ldg(Lb + sidx[l]);
        }
    }
    __syncthreads();

    // ---- phase 2a: deterministic reduction to vsh (120 threads) ----
    if (tid < 120) {
        const int vslot = tid >> 2;   // 0..29  (= f*5 + slot)
        const int ln    = tid & 3;
        const int f     = vslot / 5;
        const int s     = vslot % 5;
        float4 a;
        if (f == 2) {
            a = psum[(5 * s) * 4 + ln];
#pragma unroll
            for (int u = 1; u < 5; ++u) {
                float4 q = psum[(5 * s + u) * 4 + ln];
                a.x += q.x; a.y += q.y; a.z += q.z; a.w += q.w;
            }
        } else if (f == 3) {
            const int u0 = 25 + 2 * s;
            float4 q0 = psum[u0 * 4 + ln];
            float4 q1 = psum[(u0 + 1) * 4 + ln];
            a = make_float4(q0.x + q1.x, q0.y + q1.y, q0.z + q1.z, q0.w + q1.w);
        } else {
            const int u = ((f == 0) ? 35 : (f == 1) ? 40 : (f == 4) ? 45 : 50) + s;
            a = psum[u * 4 + ln];
        }
        const float sc = 1.0f / (float)SEQ[f];
        vsh[vslot][ln * 4 + 0] = a.x * sc;
        vsh[vslot][ln * 4 + 1] = a.y * sc;
        vsh[vslot][ln * 4 + 2] = a.z * sc;
        vsh[vslot][ln * 4 + 3] = a.w * sc;
    }
    // ---- phase 2b: per-field linear sums (6 threads) ----
    else if (tid < 126 + 0 && tid >= 120) { /* unreachable split guard */ }
    if (tid >= 128 && tid < 134) {
        const int f = tid - 128;
        float s = 0.0f;
        for (int l = OFF[f]; l < OFF[f] + SEQ[f]; ++l) s += larr[l];
        lsum[f] = s * (1.0f / (float)SEQ[f]);
    }
    __syncthreads();

    // ---- finalize: FM interaction + linear + sigmoid (warp 0) ----
    if (tid < 16) {
        float fmp = 0.0f;
#pragma unroll
        for (int i = 0; i < NF; ++i) {
#pragma unroll
            for (int j = i + 1; j < NF; ++j) {
                fmp += vsh[i * 5 + (j - 1)][tid] * vsh[j * 5 + i][tid];
            }
        }
#pragma unroll
        for (int o = 8; o > 0; o >>= 1)
            fmp += __shfl_down_sync(0x0000FFFFu, fmp, o);

        if (tid == 0) {
            float lin = __ldg(p.bd);
#pragma unroll
            for (int f = 0; f < NF; ++f)
                lin += lsum[f] * __ldg(p.Wd + f);
            lin = fmaxf(lin, 0.0f);
            const float z = lin + fmp;
            p.out[b] = 1.0f / (1.0f + __expf(-z));
        }
    }
}

extern "C" void kernel_launch(void* const* d_in, const int* in_sizes, int n_in,
                              void* d_out, int out_size) {
    FfmParams p;
    for (int i = 0; i < NF; ++i) p.x[i] = (const int*)d_in[i];   // x0..x5

    // setup_inputs() interleaves E and L: E0,L0,...,E5,L5 (auto-detect).
    const bool interleaved = (in_sizes[7] < 2000000);
    for (int i = 0; i < NF; ++i) {
        if (interleaved) {
            p.E[i] = (const float*)d_in[6 + 2 * i];
            p.L[i] = (const float*)d_in[7 + 2 * i];
        } else {
            p.E[i] = (const float*)d_in[6 + i];
            p.L[i] = (const float*)d_in[12 + i];
        }
    }
    p.Wd  = (const float*)d_in[18];
    p.bd  = (const float*)d_in[19];
    p.out = (float*)d_out;

    const int B = in_sizes[0];
    ffm_kernel<<<B, NTHREADS>>>(p);
}

// round 14
// speedup vs baseline: 3.5946x; 1.4153x over previous
#include <cuda_runtime.h>

// FFM forward: B=16384, F=6 fields, LATENT=16.
// Three-phase launch for L2 temporal locality:
//   K1 ffm_small: fields 0,1,3,4,5 (E3 table 32MB stays L2-resident)
//   K2 ffm_f2:    field 2 alone (160MB table gets all of L2)
//   K3 ffm_final: read pooled scratch, FM dots + linear + sigmoid
// Gathers are 4-lane float4 units (LDG.128), fully unrolled (MLP=10), no atomics.

#define NF    6
#define MAXB  16384

// Scratch: pooled pair embeddings (30 vslots x 16 floats per sample) + linear feats.
__device__ float g_pool[(long long)MAXB * 30 * 16];   // 31.5 MB
__device__ float g_lf[MAXB * NF];

struct FfmParams {
    const int*   x[NF];
    const float* E[NF];   // (F-1, DIMS[i], LATENT) row-major
    const float* L[NF];   // (DIMS[i], 1)
    const float* Wd;      // (F, 1)
    const float* bd;      // (1,)
    float*       out;     // (B, 1)
};

// ---------------- K1: fields 0,1,3,4,5 ----------------
// sidx layout: [0]=f0, [1]=f1, [2..22)=f3(20), [22]=f4, [23]=f5
__global__ __launch_bounds__(128) void ffm_small(FfmParams p) {
    const int b    = blockIdx.x;
    const int tid  = threadIdx.x;
    const int unit = tid >> 2;
    const int lane = tid & 3;

    __shared__ int    sidx[24];
    __shared__ float4 psum[128];
    __shared__ float  larr[24];

    if (tid == 0)       sidx[0]   = p.x[0][b];
    else if (tid == 1)  sidx[1]   = p.x[1][b];
    else if (tid < 22)  sidx[tid] = p.x[3][(long long)b * 20 + (tid - 2)];
    else if (tid == 22) sidx[22]  = p.x[4][b];
    else if (tid == 23) sidx[23]  = p.x[5][b];
    __syncthreads();

    if (unit < 10) {
        // field 3: slot = unit/2, seq chunk of 10
        const int slot = unit >> 1;
        const int s0   = (unit & 1) * 10;
        const float4* base = (const float4*)p.E[3] + (long long)slot * 100000 * 4 + lane;
        float4 a = make_float4(0.f, 0.f, 0.f, 0.f);
#pragma unroll
        for (int t = 0; t < 10; ++t) {
            float4 e = __ldg(base + (long long)sidx[2 + s0 + t] * 4);
            a.x += e.x; a.y += e.y; a.z += e.z; a.w += e.w;
        }
        psum[tid] = a;
    } else if (unit < 30) {
        // single-row fields: m 0..4 f0, 5..9 f1, 10..14 f4, 15..19 f5
        const int m = unit - 10;
        int f, ix; long long dim;
        if (m < 5)       { f = 0; ix = 0;  dim = 1000000; }
        else if (m < 10) { f = 1; ix = 1;  dim = 500000;  }
        else if (m < 15) { f = 4; ix = 22; dim = 10000;   }
        else             { f = 5; ix = 23; dim = 1000;    }
        const int slot = m % 5;
        const float4* base = (const float4*)p.E[f] + (long long)slot * dim * 4 + lane;
        psum[tid] = __ldg(base + (long long)sidx[ix] * 4);
    } else {
        // linear gather: 8 threads cover 24 indices
        const int l0 = tid - 120;
        for (int l = l0; l < 24; l += 8) {
            const float* Lb = (l == 0)  ? p.L[0]
                            : (l == 1)  ? p.L[1]
                            : (l < 22)  ? p.L[3]
                            : (l == 22) ? p.L[4] : p.L[5];
            larr[l] = __ldg(Lb + sidx[l]);
        }
    }
    __syncthreads();

    // reduce -> g_pool. 25 vslots x 4 lanes = 100 threads.
    if (tid < 100) {
        const int k  = tid >> 2;    // 0..24
        const int ln = tid & 3;
        float4 a; float sc = 1.0f; int vslot;
        if (k < 10) {               // f0 (vslot 0..4), f1 (5..9): unit = 10+k
            vslot = k;
            a = psum[(10 + k) * 4 + ln];
        } else if (k < 15) {        // f3 (vslot 15..19): units 2s, 2s+1
            vslot = 5 + k;
            const int s = k - 10;
            float4 q0 = psum[(2 * s) * 4 + ln];
            float4 q1 = psum[(2 * s + 1) * 4 + ln];
            a = make_float4(q0.x + q1.x, q0.y + q1.y, q0.z + q1.z, q0.w + q1.w);
            sc = 1.0f / 20.0f;
        } else {                    // f4 (vslot 20..24), f5 (25..29): unit = k+5
            vslot = 5 + k;
            a = psum[(k + 5) * 4 + ln];
        }
        float4 o = make_float4(a.x * sc, a.y * sc, a.z * sc, a.w * sc);
        *(float4*)&g_pool[((long long)b * 30 + vslot) * 16 + ln * 4] = o;
    } else if (tid < 105) {
        // per-field linear sums for fields {0,1,3,4,5}
        const int t = tid - 100;
        const int FF[5] = {0, 1, 3, 4, 5};
        const int LO[5] = {0, 1, 2, 22, 23};
        const int LN[5] = {1, 1, 20, 1, 1};
        float s = 0.0f;
        for (int i = 0; i < LN[t]; ++i) s += larr[LO[t] + i];
        g_lf[b * NF + FF[t]] = s / (float)LN[t];
    }
}

// ---------------- K2: field 2 ----------------
__global__ __launch_bounds__(128) void ffm_f2(FfmParams p) {
    const int b    = blockIdx.x;
    const int tid  = threadIdx.x;
    const int unit = tid >> 2;
    const int lane = tid & 3;

    __shared__ int    sidx[50];
    __shared__ float4 psum[100];
    __shared__ float  larr[50];

    if (tid < 50) sidx[tid] = p.x[2][(long long)b * 50 + tid];
    __syncthreads();

    if (unit < 25) {
        const int slot = unit / 5;
        const int s0   = (unit % 5) * 10;
        const float4* base = (const float4*)p.E[2] + (long long)slot * 500000 * 4 + lane;
        float4 a = make_float4(0.f, 0.f, 0.f, 0.f);
#pragma unroll
        for (int t = 0; t < 10; ++t) {
            float4 e = __ldg(base + (long long)sidx[s0 + t] * 4);
            a.x += e.x; a.y += e.y; a.z += e.z; a.w += e.w;
        }
        psum[tid] = a;
    } else {
        const int l = tid - 100;    // 0..27
        larr[l] = __ldg(p.L[2] + sidx[l]);
        if (l + 28 < 50) larr[l + 28] = __ldg(p.L[2] + sidx[l + 28]);
    }
    __syncthreads();

    if (tid < 20) {
        const int s  = tid >> 2;    // slot 0..4 -> vslot 10..14
        const int ln = tid & 3;
        float4 a = psum[(5 * s) * 4 + ln];
#pragma unroll
        for (int u = 1; u < 5; ++u) {
            float4 q = psum[(5 * s + u) * 4 + ln];
            a.x += q.x; a.y += q.y; a.z += q.z; a.w += q.w;
        }
        const float sc = 1.0f / 50.0f;
        float4 o = make_float4(a.x * sc, a.y * sc, a.z * sc, a.w * sc);
        *(float4*)&g_pool[((long long)b * 30 + (10 + s)) * 16 + ln * 4] = o;
    } else if (tid == 20) {
        float s = 0.0f;
        for (int l = 0; l < 50; ++l) s += larr[l];
        g_lf[b * NF + 2] = s * (1.0f / 50.0f);
    }
}

// ---------------- K3: finalize ----------------
__global__ __launch_bounds__(256) void ffm_final(FfmParams p, int B) {
    const int w    = threadIdx.x >> 5;
    const int lane = threadIdx.x & 31;
    const int b    = blockIdx.x * 8 + w;

    __shared__ __align__(16) float sv[8][480];

    if (b < B) {
        const float4* src = (const float4*)&g_pool[(long long)b * 480];
        float4* dst = (float4*)&sv[w][0];
        for (int k = lane; k < 120; k += 32) dst[k] = __ldg(src + k);
    }
    __syncwarp();

    if (b < B && lane < 16) {
        float fmp = 0.0f;
#pragma unroll
        for (int i = 0; i < NF; ++i) {
#pragma unroll
            for (int j = i + 1; j < NF; ++j) {
                fmp += sv[w][(i * 5 + (j - 1)) * 16 + lane] *
                       sv[w][(j * 5 + i) * 16 + lane];
            }
        }
#pragma unroll
        for (int o = 8; o > 0; o >>= 1)
            fmp += __shfl_down_sync(0x0000FFFFu, fmp, o);

        if (lane == 0) {
            float lin = __ldg(p.bd);
#pragma unroll
            for (int f = 0; f < NF; ++f)
                lin += g_lf[b * NF + f] * __ldg(p.Wd + f);
            lin = fmaxf(lin, 0.0f);
            const float z = lin + fmp;
            p.out[b] = 1.0f / (1.0f + __expf(-z));
        }
    }
}

extern "C" void kernel_launch(void* const* d_in, const int* in_sizes, int n_in,
                              void* d_out, int out_size) {
    FfmParams p;
    for (int i = 0; i < NF; ++i) p.x[i] = (const int*)d_in[i];   // x0..x5

    // setup_inputs() interleaves E and L: E0,L0,...,E5,L5 (auto-detect).
    const bool interleaved = (in_sizes[7] < 2000000);
    for (int i = 0; i < NF; ++i) {
        if (interleaved) {
            p.E[i] = (const float*)d_in[6 + 2 * i];
            p.L[i] = (const float*)d_in[7 + 2 * i];
        } else {
            p.E[i] = (const float*)d_in[6 + i];
            p.L[i] = (const float*)d_in[12 + i];
        }
    }
    p.Wd  = (const float*)d_in[18];
    p.bd  = (const float*)d_in[19];
    p.out = (float*)d_out;

    const int B = in_sizes[0];

    ffm_small<<<B, 128>>>(p);
    ffm_f2   <<<B, 128>>>(p);
    ffm_final<<<(B + 7) / 8, 256>>>(p, B);
}

// round 16
// speedup vs baseline: 3.7851x; 1.0530x over previous
#include <cuda_runtime.h>

// FFM forward: B=16384, F=6 fields, LATENT=16.
//   K1 ffm_k1: fields 0,1,3,4,5 gather + 10 internal FM pair dots + linear
//              partial; writes 5 "partner" vectors (for f2 pairs) + 2 scalars.
//   K2 ffm_f2: grid (B,5) slot-major -> one 32MB E2 subtable live at a time
//              (L2-resident). Block (b,s) pools 50 rows of slot s, dots with
//              its partner vector, writes one scalar.
//   K3 ffm_fin: 1 thread/sample combine + sigmoid.
// All reductions fixed-order (deterministic). No atomics.

#define NF    6
#define MAXB  16384

__device__ float g_vpart[(long long)MAXB * 5 * 16];  // partner vecs for f2 pairs
__device__ float g_fm1[MAXB];                        // 10-pair dot sum
__device__ float g_fm2[MAXB * 5];                    // per-slot f2 pair dots
__device__ float g_lin1[MAXB];                       // sum_{f!=2} meanL_f * Wd[f]
__device__ float g_lin2[MAXB];                       // meanL_2 (unweighted)

struct FfmParams {
    const int*   x[NF];
    const float* E[NF];   // (F-1, DIMS[i], LATENT) row-major
    const float* L[NF];   // (DIMS[i], 1)
    const float* Wd;      // (F, 1)
    const float* bd;      // (1,)
    float*       out;     // (B, 1)
};

// ---------------- K1: fields 0,1,3,4,5 ----------------
// Local vslot numbering: f0:0-4, f1:5-9, f3:10-14, f4:15-19, f5:20-24.
__global__ __launch_bounds__(128) void ffm_k1(FfmParams p) {
    const int b    = blockIdx.x;
    const int tid  = threadIdx.x;
    const int unit = tid >> 2;
    const int lane = tid & 3;

    __shared__ int    sidx[24];   // [0]=f0 [1]=f1 [2..22)=f3 [22]=f4 [23]=f5
    __shared__ float4 psum[128];
    __shared__ float  vsh[25][16];
    __shared__ float  larr[24];

    if (tid == 0)       sidx[0]   = p.x[0][b];
    else if (tid == 1)  sidx[1]   = p.x[1][b];
    else if (tid < 22)  sidx[tid] = p.x[3][(long long)b * 20 + (tid - 2)];
    else if (tid == 22) sidx[22]  = p.x[4][b];
    else if (tid == 23) sidx[23]  = p.x[5][b];
    __syncthreads();

    if (unit < 10) {
        // field 3: slot = unit/2, 10-seq chunk
        const int slot = unit >> 1;
        const int s0   = (unit & 1) * 10;
        const float4* base = (const float4*)p.E[3] + (long long)slot * 100000 * 4 + lane;
        float4 a = make_float4(0.f, 0.f, 0.f, 0.f);
#pragma unroll
        for (int t = 0; t < 10; ++t) {
            float4 e = __ldg(base + (long long)sidx[2 + s0 + t] * 4);
            a.x += e.x; a.y += e.y; a.z += e.z; a.w += e.w;
        }
        psum[tid] = a;
    } else if (unit < 30) {
        // single-row fields: m 0-4 f0, 5-9 f1, 10-14 f4, 15-19 f5
        const int m = unit - 10;
        int f, ix; long long dim;
        if (m < 5)       { f = 0; ix = 0;  dim = 1000000; }
        else if (m < 10) { f = 1; ix = 1;  dim = 500000;  }
        else if (m < 15) { f = 4; ix = 22; dim = 10000;   }
        else             { f = 5; ix = 23; dim = 1000;    }
        const int slot = m % 5;
        const float4* base = (const float4*)p.E[f] + (long long)slot * dim * 4 + lane;
        psum[tid] = __ldg(base + (long long)sidx[ix] * 4);
    } else {
        // linear gather: 8 threads cover 24 indices
        const int l0 = tid - 120;
        for (int l = l0; l < 24; l += 8) {
            const float* Lb = (l == 0)  ? p.L[0]
                            : (l == 1)  ? p.L[1]
                            : (l < 22)  ? p.L[3]
                            : (l == 22) ? p.L[4] : p.L[5];
            larr[l] = __ldg(Lb + sidx[l]);
        }
    }
    __syncthreads();

    // reduce -> vsh (100 threads): k = local vslot
    if (tid < 100) {
        const int k  = tid >> 2;
        const int ln = tid & 3;
        float4 a; float sc = 1.0f;
        if (k < 10) {                       // f0 (0-4), f1 (5-9): unit 10+k
            a = psum[(10 + k) * 4 + ln];
        } else if (k < 15) {                // f3 (10-14): units 2s, 2s+1
            const int s = k - 10;
            float4 q0 = psum[(2 * s) * 4 + ln];
            float4 q1 = psum[(2 * s + 1) * 4 + ln];
            a = make_float4(q0.x + q1.x, q0.y + q1.y, q0.z + q1.z, q0.w + q1.w);
            sc = 1.0f / 20.0f;
        } else {                            // f4 (15-19), f5 (20-24): unit k+5
            a = psum[(k + 5) * 4 + ln];
        }
        vsh[k][ln * 4 + 0] = a.x * sc;
        vsh[k][ln * 4 + 1] = a.y * sc;
        vsh[k][ln * 4 + 2] = a.z * sc;
        vsh[k][ln * 4 + 3] = a.w * sc;
    }
    __syncthreads();

    // 10 internal FM pairs (local vslot ids)
    if (tid < 16) {
        constexpr int PA[10] = {0, 2, 3,  4,  7,  8,  9, 13, 14, 19};
        constexpr int PB[10] = {5, 10, 15, 20, 11, 16, 21, 18, 23, 24};
        float fmp = 0.0f;
#pragma unroll
        for (int t = 0; t < 10; ++t)
            fmp += vsh[PA[t]][tid] * vsh[PB[t]][tid];
#pragma unroll
        for (int o = 8; o > 0; o >>= 1)
            fmp += __shfl_down_sync(0x0000FFFFu, fmp, o);
        if (tid == 0) g_fm1[b] = fmp;
    } else if (tid >= 32 && tid < 52) {
        // write the 5 partner vectors for f2: locals {1,6,12,17,22}
        constexpr int VP[5] = {1, 6, 12, 17, 22};
        const int k  = (tid - 32) >> 2;
        const int ln = (tid - 32) & 3;
        float4 o = *(const float4*)&vsh[VP[k]][ln * 4];
        *(float4*)&g_vpart[((long long)b * 5 + k) * 16 + ln * 4] = o;
    } else if (tid == 64) {
        // linear partial for fields {0,1,3,4,5}
        constexpr int FF[5] = {0, 1, 3, 4, 5};
        constexpr int LO[5] = {0, 1, 2, 22, 23};
        constexpr int LN[5] = {1, 1, 20, 1, 1};
        float lin = 0.0f;
#pragma unroll
        for (int t = 0; t < 5; ++t) {
            float s = 0.0f;
            for (int i = 0; i < LN[t]; ++i) s += larr[LO[t] + i];
            lin += (s / (float)LN[t]) * __ldg(p.Wd + FF[t]);
        }
        g_lin1[b] = lin;
    }
}

// ---------------- K2: field 2, slot-phased ----------------
// grid (B, 5); blockIdx.y = slot (slow dim -> slot-major execution).
__global__ __launch_bounds__(64) void ffm_f2(FfmParams p) {
    const int b    = blockIdx.x;
    const int s    = blockIdx.y;
    const int tid  = threadIdx.x;
    const int unit = tid >> 2;     // 0..15
    const int lane = tid & 3;

    __shared__ int    sidx[50];
    __shared__ float4 psum[64];
    __shared__ float  larr[50];

    if (tid < 50) sidx[tid] = p.x[2][(long long)b * 50 + tid];
    __syncthreads();

    // gather: unit u handles rows u, u+16, u+32 (+48 for u<2)
    {
        const float4* base = (const float4*)p.E[2] + (long long)s * 500000 * 4 + lane;
        float4 e0 = __ldg(base + (long long)sidx[unit] * 4);
        float4 e1 = __ldg(base + (long long)sidx[unit + 16] * 4);
        float4 e2 = __ldg(base + (long long)sidx[unit + 32] * 4);
        float4 a = make_float4(e0.x + e1.x + e2.x, e0.y + e1.y + e2.y,
                               e0.z + e1.z + e2.z, e0.w + e1.w + e2.w);
        if (unit < 2) {
            float4 e3 = __ldg(base + (long long)sidx[unit + 48] * 4);
            a.x += e3.x; a.y += e3.y; a.z += e3.z; a.w += e3.w;
        }
        psum[tid] = a;
        if (s == 0 && tid < 50) larr[tid] = __ldg(p.L[2] + sidx[tid]);
    }
    __syncthreads();

    // reduce 16 units -> 16-elem vector, dot with partner, write scalar
    if (tid < 16) {
        const int ln = tid >> 2;   // float4 lane of element tid
        const int c  = tid & 3;    // component
        float ve = 0.0f;
#pragma unroll
        for (int u = 0; u < 16; ++u) {
            const float4 q = psum[u * 4 + ln];
            ve += (c == 0) ? q.x : (c == 1) ? q.y : (c == 2) ? q.z : q.w;
        }
        const float partner = __ldg(&g_vpart[((long long)b * 5 + s) * 16 + tid]);
        float prod = ve * partner;
#pragma unroll
        for (int o = 8; o > 0; o >>= 1)
            prod += __shfl_down_sync(0x0000FFFFu, prod, o);
        if (tid == 0) g_fm2[b * 5 + s] = prod * (1.0f / 50.0f);
    } else if (s == 0 && tid == 16) {
        float sum = 0.0f;
        for (int l = 0; l < 50; ++l) sum += larr[l];
        g_lin2[b] = sum * (1.0f / 50.0f);
    }
}

// ---------------- K3: combine ----------------
__global__ __launch_bounds__(256) void ffm_fin(FfmParams p, int B) {
    const int b = blockIdx.x * 256 + threadIdx.x;
    if (b >= B) return;
    float fm = g_fm1[b];
#pragma unroll
    for (int s = 0; s < 5; ++s) fm += g_fm2[b * 5 + s];
    float lin = g_lin1[b] + g_lin2[b] * __ldg(p.Wd + 2) + __ldg(p.bd);
    lin = fmaxf(lin, 0.0f);
    const float z = lin + fm;
    p.out[b] = 1.0f / (1.0f + __expf(-z));
}

extern "C" void kernel_launch(void* const* d_in, const int* in_sizes, int n_in,
                              void* d_out, int out_size) {
    FfmParams p;
    for (int i = 0; i < NF; ++i) p.x[i] = (const int*)d_in[i];   // x0..x5

    // setup_inputs() interleaves E and L: E0,L0,...,E5,L5 (auto-detect).
    const bool interleaved = (in_sizes[7] < 2000000);
    for (int i = 0; i < NF; ++i) {
        if (interleaved) {
            p.E[i] = (const float*)d_in[6 + 2 * i];
            p.L[i] = (const float*)d_in[7 + 2 * i];
        } else {
            p.E[i] = (const float*)d_in[6 + i];
            p.L[i] = (const float*)d_in[12 + i];
        }
    }
    p.Wd  = (const float*)d_in[18];
    p.bd  = (const float*)d_in[19];
    p.out = (float*)d_out;

    const int B = in_sizes[0];

    ffm_k1<<<B, 128>>>(p);
    dim3 g2(B, 5);
    ffm_f2<<<g2, 64>>>(p);
    ffm_fin<<<(B + 255) / 256, 256>>>(p, B);
}